// round 10
// baseline (speedup 1.0000x reference)
#include <cuda_runtime.h>
#include <cstdint>

// CTC batch cost, forward (loss only). B=128, T=1024, C=256 (blank=255),
// Lmax=64, S=129.
//
//  - one warp (one CTA) per batch element; 5 states/thread (160 >= 129, masked)
//  - probability-domain recurrence, per-thread block-floating-point scales,
//    frontier-safe scan renorm for first 16 chunks (R5 numerics, 1.5e-6)
//  - BULK-COPY STREAMING (resubmit of R9; R9 bench died to infra, same error
//    signature as the round-0 stub). cp.async (LDGSTS) is capped at ~55
//    outstanding ops/warp => in-flight bytes stuck at ~11KB/CTA regardless of
//    ring size (R8 flat). Ring fill is ONE 8KB cp.async.bulk per 8-row chunk
//    (contiguous in gmem), mbarrier complete_tx per ring slot, lane 0 issues.
//    14 chunks x 8KB = 112KB genuinely in flight per CTA via the bulk engine.
//  - R10 tweak: parity wait uses try_wait with suspend hint (HW sleep, no
//    issue-slot burn) instead of a hot poll loop.

#define T_DIM   1024
#define C_DIM   256
#define LMAX    64
#define PSTATES 5
#define CHUNK   8
#define RINGC   16
#define NCHUNK  (T_DIM / CHUNK)          // 128
#define SCANCH  16
#define EPSF    1e-7f
#define MFLOOR  1e-37f
#define CHUNK_BYTES (CHUNK * C_DIM * 4)  // 8192
#define RING_BYTES  (RINGC * CHUNK_BYTES) // 131072

__global__ __launch_bounds__(32, 1)
void ctc_loss_kernel(const int*   __restrict__ y_true,   // [B, LMAX]
                     const float* __restrict__ y_pred,   // [B, T, C]
                     const int*   __restrict__ in_len,   // [B, 1]
                     const int*   __restrict__ lab_len,  // [B, 1]
                     float*       __restrict__ out)      // [B, 1]
{
    extern __shared__ __align__(128) float stage[];      // RINGC * 8KB ring
    __shared__ __align__(8) uint64_t mbar[RINGC];
    __shared__ float fin_a [32 * PSTATES];
    __shared__ float fin_lc[32];

    const int b   = blockIdx.x;
    const int tid = threadIdx.x;
    const char* __restrict__ gbase =
        (const char*)(y_pred + (size_t)b * T_DIM * C_DIM);
    const int L    = lab_len[b];
    const int Tlen = in_len[b];
    const int Smax = 2 * L + 1;
    const int* __restrict__ yb = y_true + b * LMAX;

    // generic -> shared address conversion
    uint32_t stage_addr, mbar_addr;
    asm("{ .reg .u64 t; cvta.to.shared.u64 t, %1; cvt.u32.u64 %0, t; }"
        : "=r"(stage_addr) : "l"((const void*)stage));
    asm("{ .reg .u64 t; cvta.to.shared.u64 t, %1; cvt.u32.u64 %0, t; }"
        : "=r"(mbar_addr) : "l"((const void*)mbar));

    // ---- per-state constants ----
    int   cls[PSTATES];
    float vm [PSTATES];
    float evm[PSTATES];
    float m2 [PSTATES];
    #pragma unroll
    for (int j = 0; j < PSTATES; j++) {
        int s   = tid * PSTATES + j;
        int odd = s & 1;
        int li  = (s - 1) >> 1;
        int c   = (odd && li >= 0 && li < LMAX) ? yb[li] : (C_DIM - 1);
        bool valid = (s < Smax);
        cls[j] = c;
        vm [j] = valid ? 1.0f : 0.0f;
        evm[j] = valid ? EPSF : 0.0f;
        bool skip = odd && (s >= 3) && (li < LMAX) && (yb[li] != yb[li - 1]);
        m2 [j] = skip ? 1.0f : 0.0f;
    }

    // ---- mbarrier init (count 1; tx-based completion) ----
    if (tid == 0) {
        #pragma unroll
        for (int s = 0; s < RINGC; s++)
            asm volatile("mbarrier.init.shared.b64 [%0], 1;"
                         :: "r"(mbar_addr + s * 8) : "memory");
        asm volatile("fence.proxy.async.shared::cta;" ::: "memory");
    }
    __syncwarp();

    // ---- issue one 8KB bulk copy for chunk c (lane 0 only) ----
    auto issue_chunk = [&](int c) {
        if (tid == 0 && c < NCHUNK) {
            uint32_t slot = (uint32_t)c & (RINGC - 1);
            uint32_t mb   = mbar_addr + slot * 8;
            uint32_t dst  = stage_addr + slot * CHUNK_BYTES;
            const char* src = gbase + (size_t)c * CHUNK_BYTES;
            asm volatile(
                "mbarrier.arrive.expect_tx.shared::cta.b64 _, [%0], %1;"
                :: "r"(mb), "n"(CHUNK_BYTES) : "memory");
            asm volatile(
                "cp.async.bulk.shared::cluster.global.mbarrier::complete_tx::bytes"
                " [%0], [%1], %2, [%3];"
                :: "r"(dst), "l"(src), "n"(CHUNK_BYTES), "r"(mb) : "memory");
        }
    };

    // ---- wait for chunk c resident (all threads; HW-sleep try_wait) ----
    auto wait_chunk = [&](int c) {
        uint32_t mb     = mbar_addr + ((uint32_t)c & (RINGC - 1)) * 8;
        uint32_t parity = ((uint32_t)c >> 4) & 1u;
        asm volatile(
            "{\n\t.reg .pred P;\n\t"
            "W_%=:\n\t"
            "mbarrier.try_wait.parity.acquire.cta.shared::cta.b64 P, [%0], %1, 0x989680;\n\t"
            "@!P bra W_%=;\n\t}"
            :: "r"(mb), "r"(parity) : "memory");
    };

    float a[PSTATES];
    float logacc = 0.0f;                       // log sigma_i (per-thread scale)
    float rho    = (tid == 0) ? 0.0f : 1.0f;   // lane0 rho=0 == m1 mask

    auto step1 = [&](int t, const float* __restrict__ row) {
        if (t < Tlen) {
            float h1 = __shfl_up_sync(0xffffffffu, a[4], 1) * rho;
            float h2 = __shfl_up_sync(0xffffffffu, a[3], 1) * rho;
            float p0 = fmaf(row[cls[0]], vm[0], evm[0]);
            float p1 = fmaf(row[cls[1]], vm[1], evm[1]);
            float p2 = fmaf(row[cls[2]], vm[2], evm[2]);
            float p3 = fmaf(row[cls[3]], vm[3], evm[3]);
            float p4 = fmaf(row[cls[4]], vm[4], evm[4]);
            float n0 = fmaf(h2,   m2[0], a[0] + h1)   * p0;
            float n1 = fmaf(h1,   m2[1], a[1] + a[0]) * p1;
            float n2 = fmaf(a[0], m2[2], a[2] + a[1]) * p2;
            float n3 = fmaf(a[1], m2[3], a[3] + a[2]) * p3;
            float n4 = fmaf(a[2], m2[4], a[4] + a[3]) * p4;
            a[0] = n0; a[1] = n1; a[2] = n2; a[3] = n3; a[4] = n4;
        }
    };

    auto apply_scale = [&](float v) {
        float mprev = __shfl_up_sync(0xffffffffu, v, 1);   // lane0: own v
        float rinv  = __fdividef(1.0f, v);
        logacc += __logf(v);
        rho = fminf(rho * (mprev * rinv), 1e30f);          // lane0 stays 0
        #pragma unroll
        for (int j = 0; j < PSTATES; j++) a[j] *= rinv;
    };

    auto renorm_scan = [&]() {       // frontier-safe: adopt nearest active below
        float lm = fmaxf(fmaxf(fmaxf(a[0], a[1]), fmaxf(a[2], a[3])), a[4]);
        float v  = lm;
        #pragma unroll
        for (int d = 1; d < 32; d <<= 1) {
            float up = __shfl_up_sync(0xffffffffu, v, d);
            v = (v > 0.0f) ? v : up;
        }
        v = fmaxf(v, MFLOOR);
        apply_scale(v);
    };

    auto renorm_fast = [&]() {
        float lm = fmaxf(fmaxf(fmaxf(a[0], a[1]), fmaxf(a[2], a[3])), a[4]);
        apply_scale(fmaxf(lm, MFLOOR));
    };

    // ---- prologue: issue chunks 0..RINGC-2 (15 x 8KB in flight) ----
    for (int c = 0; c < RINGC - 1; c++) issue_chunk(c);

    // ---- chunk 0 ----
    wait_chunk(0);
    __syncwarp();
    issue_chunk(RINGC - 1);
    {
        const float* __restrict__ row0 = &stage[0];
        #pragma unroll
        for (int j = 0; j < PSTATES; j++) {
            int s   = tid * PSTATES + j;
            float p = fmaf(row0[cls[j]], vm[j], evm[j]);
            a[j]    = (s < 2) ? p : 0.0f;
        }
        #pragma unroll
        for (int i = 1; i < CHUNK; i++) step1(i, &stage[i * C_DIM]);
    }
    renorm_scan();

    // ---- chunks 1..127 ----
    for (int c = 1; c < NCHUNK; c++) {
        wait_chunk(c);
        __syncwarp();                        // all lanes done reading slot c-1
        issue_chunk(c + RINGC - 1);          // overwrite slot (c-1)&15
        const int base_row = (c & (RINGC - 1)) * CHUNK;
        const int t0 = c * CHUNK;
        #pragma unroll
        for (int i = 0; i < CHUNK; i++)
            step1(t0 + i, &stage[(base_row + i) * C_DIM]);
        if (c < SCANCH) renorm_scan(); else renorm_fast();
    }

    // ---- finalize: ll = logaddexp over the two end states ----
    __syncwarp();
    #pragma unroll
    for (int j = 0; j < PSTATES; j++) fin_a[tid * PSTATES + j] = a[j];
    fin_lc[tid] = logacc;
    __syncwarp();
    if (tid == 0) {
        int  sa = 2 * L;
        int  sb = 2 * L - 1;                  // L >= 1 per setup
        float xa = __logf(fmaxf(fin_a[sa], MFLOOR)) + fin_lc[sa / PSTATES];
        float xb = __logf(fmaxf(fin_a[sb], MFLOOR)) + fin_lc[sb / PSTATES];
        float mxx = fmaxf(xa, xb);
        float mnn = fminf(xa, xb);
        float ll  = mxx + __logf(1.0f + __expf(mnn - mxx));
        out[b] = -ll;
    }
}

extern "C" void kernel_launch(void* const* d_in, const int* in_sizes, int n_in,
                              void* d_out, int out_size) {
    const int*   y_true  = (const int*)  d_in[0];   // [B,64] int32
    const float* y_pred  = (const float*)d_in[1];   // [B,1024,256] fp32
    const int*   in_len  = (const int*)  d_in[2];   // [B,1] int32
    const int*   lab_len = (const int*)  d_in[3];   // [B,1] int32
    float*       out     = (float*)      d_out;     // [B,1] fp32

    cudaFuncSetAttribute(ctc_loss_kernel,
                         cudaFuncAttributeMaxDynamicSharedMemorySize,
                         RING_BYTES);

    const int B = out_size;                          // 128
    ctc_loss_kernel<<<B, 32, RING_BYTES>>>(y_true, y_pred, in_len, lab_len, out);
}

// round 11
// speedup vs baseline: 1.5800x; 1.5800x over previous
#include <cuda_runtime.h>
#include <cstdint>

// CTC batch cost, forward (loss only). B=128, T=1024, C=256 (blank=255),
// Lmax=64, S=129.
//
//  - one warp (one CTA) per batch element; 5 states/thread (160 >= 129, masked)
//  - probability-domain recurrence, per-thread block-floating-point scales,
//    frontier-safe scan renorm for t<128 (R5 numerics, rel_err 1.5e-6)
//  - bulk-copy streaming ring (R10): one cp.async.bulk per chunk, mbarrier
//    complete_tx per slot, lane 0 issues; ring full in steady state.
//  - THIS ROUND (overhead strip):
//    1. POWER-OF-2 RENORM: scale by 2^e via exponent bit ops; integer
//       log-accumulator. No MUFU logf/fdividef in the loop. Exact bookkeeping.
//    2. 16-STEP CHUNKS: 8 ring slots x 16KB; wait/sync/issue overhead halved.
//    3. Tlen GUARD HOISTED to chunk granularity: 16 branch-free steps per
//       chunk on the fast path; per-step guards only in the boundary chunk.

#define T_DIM   1024
#define C_DIM   256
#define LMAX    64
#define PSTATES 5
#define CHUNK   16                        // rows per ring slot / wait
#define RINGC   8                         // ring slots
#define NCHUNK  (T_DIM / CHUNK)           // 64
#define SCANCH  8                         // chunks (t<128) using scan renorm
#define EPSF    1e-7f
#define MFLOOR  1e-37f
#define CHUNK_BYTES (CHUNK * C_DIM * 4)   // 16384
#define RING_BYTES  (RINGC * CHUNK_BYTES) // 131072

__global__ __launch_bounds__(32, 1)
void ctc_loss_kernel(const int*   __restrict__ y_true,   // [B, LMAX]
                     const float* __restrict__ y_pred,   // [B, T, C]
                     const int*   __restrict__ in_len,   // [B, 1]
                     const int*   __restrict__ lab_len,  // [B, 1]
                     float*       __restrict__ out)      // [B, 1]
{
    extern __shared__ __align__(128) float stage[];      // RINGC * 16KB ring
    __shared__ __align__(8) uint64_t mbar[RINGC];
    __shared__ float fin_a [32 * PSTATES];
    __shared__ float fin_lc[32];

    const int b   = blockIdx.x;
    const int tid = threadIdx.x;
    const char* __restrict__ gbase =
        (const char*)(y_pred + (size_t)b * T_DIM * C_DIM);
    const int L    = lab_len[b];
    const int Tlen = in_len[b];
    const int Smax = 2 * L + 1;
    const int* __restrict__ yb = y_true + b * LMAX;

    uint32_t stage_addr, mbar_addr;
    asm("{ .reg .u64 t; cvta.to.shared.u64 t, %1; cvt.u32.u64 %0, t; }"
        : "=r"(stage_addr) : "l"((const void*)stage));
    asm("{ .reg .u64 t; cvta.to.shared.u64 t, %1; cvt.u32.u64 %0, t; }"
        : "=r"(mbar_addr) : "l"((const void*)mbar));

    // ---- per-state constants ----
    int   cls[PSTATES];
    float vm [PSTATES];
    float evm[PSTATES];
    float m2 [PSTATES];
    #pragma unroll
    for (int j = 0; j < PSTATES; j++) {
        int s   = tid * PSTATES + j;
        int odd = s & 1;
        int li  = (s - 1) >> 1;
        int c   = (odd && li >= 0 && li < LMAX) ? yb[li] : (C_DIM - 1);
        bool valid = (s < Smax);
        cls[j] = c;
        vm [j] = valid ? 1.0f : 0.0f;
        evm[j] = valid ? EPSF : 0.0f;
        bool skip = odd && (s >= 3) && (li < LMAX) && (yb[li] != yb[li - 1]);
        m2 [j] = skip ? 1.0f : 0.0f;
    }

    // ---- mbarrier init ----
    if (tid == 0) {
        #pragma unroll
        for (int s = 0; s < RINGC; s++)
            asm volatile("mbarrier.init.shared.b64 [%0], 1;"
                         :: "r"(mbar_addr + s * 8) : "memory");
        asm volatile("fence.proxy.async.shared::cta;" ::: "memory");
    }
    __syncwarp();

    // ---- issue one 16KB bulk copy for chunk c (lane 0 only) ----
    auto issue_chunk = [&](int c) {
        if (tid == 0 && c < NCHUNK) {
            uint32_t slot = (uint32_t)c & (RINGC - 1);
            uint32_t mb   = mbar_addr + slot * 8;
            uint32_t dst  = stage_addr + slot * CHUNK_BYTES;
            const char* src = gbase + (size_t)c * CHUNK_BYTES;
            asm volatile(
                "mbarrier.arrive.expect_tx.shared::cta.b64 _, [%0], %1;"
                :: "r"(mb), "n"(CHUNK_BYTES) : "memory");
            asm volatile(
                "cp.async.bulk.shared::cluster.global.mbarrier::complete_tx::bytes"
                " [%0], [%1], %2, [%3];"
                :: "r"(dst), "l"(src), "n"(CHUNK_BYTES), "r"(mb) : "memory");
        }
    };

    auto wait_chunk = [&](int c) {
        uint32_t mb     = mbar_addr + ((uint32_t)c & (RINGC - 1)) * 8;
        uint32_t parity = ((uint32_t)c >> 3) & 1u;
        asm volatile(
            "{\n\t.reg .pred P;\n\t"
            "W_%=:\n\t"
            "mbarrier.try_wait.parity.acquire.cta.shared::cta.b64 P, [%0], %1, 0x989680;\n\t"
            "@!P bra W_%=;\n\t}"
            :: "r"(mb), "r"(parity) : "memory");
    };

    float a[PSTATES];
    int   ilogacc = 0;                         // power-of-2 exponent accumulator
    float rho     = (tid == 0) ? 0.0f : 1.0f;  // lane0 rho=0 == m1 mask

    // unguarded step (fast path; t < Tlen guaranteed by caller)
    auto step1u = [&](const float* __restrict__ row) {
        float h1 = __shfl_up_sync(0xffffffffu, a[4], 1) * rho;
        float h2 = __shfl_up_sync(0xffffffffu, a[3], 1) * rho;
        float p0 = fmaf(row[cls[0]], vm[0], evm[0]);
        float p1 = fmaf(row[cls[1]], vm[1], evm[1]);
        float p2 = fmaf(row[cls[2]], vm[2], evm[2]);
        float p3 = fmaf(row[cls[3]], vm[3], evm[3]);
        float p4 = fmaf(row[cls[4]], vm[4], evm[4]);
        float n0 = fmaf(h2,   m2[0], a[0] + h1)   * p0;
        float n1 = fmaf(h1,   m2[1], a[1] + a[0]) * p1;
        float n2 = fmaf(a[0], m2[2], a[2] + a[1]) * p2;
        float n3 = fmaf(a[1], m2[3], a[3] + a[2]) * p3;
        float n4 = fmaf(a[2], m2[4], a[4] + a[3]) * p4;
        a[0] = n0; a[1] = n1; a[2] = n2; a[3] = n3; a[4] = n4;
    };

    auto step1g = [&](int t, const float* __restrict__ row) {
        if (t < Tlen) step1u(row);
    };

    // power-of-2 scale application: v > 0 normal float
    auto apply_scale = [&](float v) {
        int ebits = __float_as_int(v) >> 23;              // biased exponent
        int eprev = __shfl_up_sync(0xffffffffu, ebits, 1); // lane0: own
        ilogacc += ebits - 127;
        float rinv = __int_as_float((254 - ebits) << 23);  // 2^(127-e)
        int d = eprev - ebits;
        d = (d > 60) ? 60 : ((d < -126) ? -126 : d);
        rho = fminf(rho * __int_as_float((d + 127) << 23), 1e30f);
        #pragma unroll
        for (int j = 0; j < PSTATES; j++) a[j] *= rinv;
    };

    auto renorm_scan = [&]() {       // frontier-safe: adopt nearest active below
        float lm = fmaxf(fmaxf(fmaxf(a[0], a[1]), fmaxf(a[2], a[3])), a[4]);
        float v  = lm;
        #pragma unroll
        for (int d = 1; d < 32; d <<= 1) {
            float up = __shfl_up_sync(0xffffffffu, v, d);
            v = (v > 0.0f) ? v : up;
        }
        apply_scale(fmaxf(v, MFLOOR));
    };

    auto renorm_fast = [&]() {
        float lm = fmaxf(fmaxf(fmaxf(a[0], a[1]), fmaxf(a[2], a[3])), a[4]);
        apply_scale(fmaxf(lm, MFLOOR));
    };

    // ---- prologue: issue chunks 0..RINGC-2 (7 x 16KB = 112KB in flight) ----
    for (int c = 0; c < RINGC - 1; c++) issue_chunk(c);

    // ---- chunk 0: init at t=0, guarded steps 1..15, renorms at 7 and 15 ----
    wait_chunk(0);
    __syncwarp();
    issue_chunk(RINGC - 1);
    {
        const float* __restrict__ row0 = &stage[0];
        #pragma unroll
        for (int j = 0; j < PSTATES; j++) {
            int s   = tid * PSTATES + j;
            float p = fmaf(row0[cls[j]], vm[j], evm[j]);
            a[j]    = (s < 2) ? p : 0.0f;
        }
        #pragma unroll
        for (int i = 1; i < 8; i++) step1g(i, &stage[i * C_DIM]);
        renorm_scan();
        #pragma unroll
        for (int i = 8; i < CHUNK; i++) step1g(i, &stage[i * C_DIM]);
        renorm_scan();
    }

    // ---- chunks 1..63 ----
    for (int c = 1; c < NCHUNK; c++) {
        wait_chunk(c);
        __syncwarp();                        // all lanes done with slot c-1
        issue_chunk(c + RINGC - 1);
        const float* __restrict__ rows = &stage[(c & (RINGC - 1)) * CHUNK * C_DIM];
        const int t0 = c * CHUNK;
        const bool scan = (c < SCANCH);
        if (t0 + CHUNK <= Tlen) {            // fast path: branch-free 16 steps
            #pragma unroll
            for (int i = 0; i < 8; i++) step1u(rows + i * C_DIM);
            if (scan) renorm_scan(); else renorm_fast();
            #pragma unroll
            for (int i = 8; i < CHUNK; i++) step1u(rows + i * C_DIM);
            if (scan) renorm_scan(); else renorm_fast();
        } else {                             // boundary chunk: per-step guards
            #pragma unroll
            for (int i = 0; i < 8; i++) step1g(t0 + i, rows + i * C_DIM);
            if (scan) renorm_scan(); else renorm_fast();
            #pragma unroll
            for (int i = 8; i < CHUNK; i++) step1g(t0 + i, rows + i * C_DIM);
            if (scan) renorm_scan(); else renorm_fast();
        }
    }

    // ---- finalize: ll = logaddexp over the two end states ----
    __syncwarp();
    #pragma unroll
    for (int j = 0; j < PSTATES; j++) fin_a[tid * PSTATES + j] = a[j];
    fin_lc[tid] = (float)ilogacc * 0.6931471805599453f;
    __syncwarp();
    if (tid == 0) {
        int  sa = 2 * L;
        int  sb = 2 * L - 1;                  // L >= 1 per setup
        float xa = __logf(fmaxf(fin_a[sa], MFLOOR)) + fin_lc[sa / PSTATES];
        float xb = __logf(fmaxf(fin_a[sb], MFLOOR)) + fin_lc[sb / PSTATES];
        float mxx = fmaxf(xa, xb);
        float mnn = fminf(xa, xb);
        float ll  = mxx + __logf(1.0f + __expf(mnn - mxx));
        out[b] = -ll;
    }
}

extern "C" void kernel_launch(void* const* d_in, const int* in_sizes, int n_in,
                              void* d_out, int out_size) {
    const int*   y_true  = (const int*)  d_in[0];   // [B,64] int32
    const float* y_pred  = (const float*)d_in[1];   // [B,1024,256] fp32
    const int*   in_len  = (const int*)  d_in[2];   // [B,1] int32
    const int*   lab_len = (const int*)  d_in[3];   // [B,1] int32
    float*       out     = (float*)      d_out;     // [B,1] fp32

    cudaFuncSetAttribute(ctc_loss_kernel,
                         cudaFuncAttributeMaxDynamicSharedMemorySize,
                         RING_BYTES);

    const int B = out_size;                          // 128
    ctc_loss_kernel<<<B, 32, RING_BYTES>>>(y_true, y_pred, in_len, lab_len, out);
}